// round 7
// baseline (speedup 1.0000x reference)
#include <cuda_runtime.h>
#include <cuda_bf16.h>
#include <cuda_fp16.h>
#include <math.h>
#include <stdint.h>

// ---------------------------------------------------------------------------
#define FDIM 128
#define DDEG 16
#define KH   2048
#define ODIM 256
#define JS   16
#define JCH  (KH/JS)
#define NMAX 100000

// Scratch (device globals; no allocation allowed)
__device__ float g_Mpart[JS][2][FDIM][ODIM];                 // 4 MB partials
__device__ __align__(16) __nv_bfloat16 g_Bhi[ODIM * 256];    // B[o][k] hi
__device__ __align__(16) __nv_bfloat16 g_Blo[ODIM * 256];    // B[o][k] lo
__device__ __align__(16) __half g_xh[NMAX * FDIM];           // fp16 shadow of x (25.6 MB)

// ---------------------------------------------------------------------------
// Kernel X: x fp32 -> fp16 shadow (read 51MB, write 26MB, ~8us)
// ---------------------------------------------------------------------------
__global__ void __launch_bounds__(256)
kX(const float* __restrict__ x, int total2)
{
    int i = blockIdx.x * 256 + threadIdx.x;
    int stride = gridDim.x * 256;
    for (; i < total2; i += stride) {
        float2 v = *(const float2*)(x + 2 * i);
        *(__half2*)(g_xh + 2 * i) = __floats2half2_rn(v.x, v.y);
    }
}

// ---------------------------------------------------------------------------
// Kernel A: partial M[m][f][o] over a 128-wide j chunk (~14us)
// ---------------------------------------------------------------------------
__global__ void __launch_bounds__(256)
kA(const float* __restrict__ R, const float* __restrict__ Ws,
   const float* __restrict__ Wn)
{
    __shared__ float sA[32][68];
    __shared__ float sB[32][68];

    const int ft = blockIdx.x, ot = blockIdx.y, mz = blockIdx.z;
    const int m = mz / JS, jc = mz % JS;
    const float* __restrict__ W = m ? Wn : Ws;
    const int f0 = ft * 64, o0 = ot * 64;
    const int jbase = jc * JCH;
    const int kk = jbase >> 8, hb = jbase & 255;
    const int tid = threadIdx.x, tx = tid & 15, ty = tid >> 4;

    float acc[4][4];
    #pragma unroll
    for (int i = 0; i < 4; i++)
        #pragma unroll
        for (int j = 0; j < 4; j++) acc[i][j] = 0.f;

    for (int jt = 0; jt < JCH; jt += 32) {
        #pragma unroll
        for (int r = 0; r < 2; r++) {
            int li = tid + r * 256;
            int f_l = li >> 3, jj = (li & 7) * 4;
            float4 a4 = *(const float4*)(R + (size_t)kk * (FDIM * 256)
                                           + (size_t)(f0 + f_l) * 256 + hb + jt + jj);
            sA[jj + 0][f_l] = a4.x; sA[jj + 1][f_l] = a4.y;
            sA[jj + 2][f_l] = a4.z; sA[jj + 3][f_l] = a4.w;
        }
        #pragma unroll
        for (int r = 0; r < 2; r++) {
            int li = tid + r * 256;
            int o_l = li >> 3, jj = (li & 7) * 4;
            float4 b4 = *(const float4*)(W + (size_t)(o0 + o_l) * KH + jbase + jt + jj);
            sB[jj + 0][o_l] = b4.x; sB[jj + 1][o_l] = b4.y;
            sB[jj + 2][o_l] = b4.z; sB[jj + 3][o_l] = b4.w;
        }
        __syncthreads();
        #pragma unroll
        for (int jj = 0; jj < 32; jj++) {
            float4 a4 = *(const float4*)&sA[jj][ty * 4];
            float4 b4 = *(const float4*)&sB[jj][tx * 4];
            float a[4] = {a4.x, a4.y, a4.z, a4.w};
            float b[4] = {b4.x, b4.y, b4.z, b4.w};
            #pragma unroll
            for (int i = 0; i < 4; i++)
                #pragma unroll
                for (int j = 0; j < 4; j++) acc[i][j] += a[i] * b[j];
        }
        __syncthreads();
    }
    float* outp = &g_Mpart[jc][m][0][0];
    #pragma unroll
    for (int i = 0; i < 4; i++) {
        float4 v = make_float4(acc[i][0], acc[i][1], acc[i][2], acc[i][3]);
        *(float4*)(outp + (size_t)(f0 + ty * 4 + i) * ODIM + o0 + tx * 4) = v;
    }
}

// Reduce partials, split to bf16 hi/lo, transpose to B[o][k], k = m*128+f.
__global__ void __launch_bounds__(256)
kReduce()
{
    int i = blockIdx.x * 256 + threadIdx.x;  // [m][f][o]
    const float* p = (const float*)g_Mpart;
    float s = 0.f;
    #pragma unroll
    for (int q = 0; q < JS; q++) s += p[(size_t)q * 2 * FDIM * ODIM + i];
    int m = i >> 15, f = (i >> 8) & 127, o = i & 255;
    int k = m * 128 + f;
    __nv_bfloat16 h = __float2bfloat16_rn(s);
    float r = s - __bfloat162float(h);
    g_Bhi[o * 256 + k] = h;
    g_Blo[o * 256 + k] = __float2bfloat16_rn(r);
}

// ---------------------------------------------------------------------------
// kB_mma: 64 nodes/CTA, 128 threads, 2 CTAs/SM.
//   Gather: warp-cooperative over fp16 shadow rows (256B/row, 2 lines/LDG).
//   B:      cp.async double-buffered 32-k chunks.
//   GEMM:   ldmatrix + mma.sync m16n8k16 bf16, 3-pass split-bf16.
// ---------------------------------------------------------------------------
#define AS 264   // A smem row stride (bf16): conflict-free LDSM
#define BS2 40   // B chunk smem row stride (bf16): conflict-free LDSM

#define SM_AH 0
#define SM_AL (SM_AH + 64 * AS * 2)            // 33792
#define SM_BB (SM_AL + 64 * AS * 2)            // 67584: 4 x (128*BS2*2 = 10240)
#define SM_IX (SM_BB + 4 * 128 * BS2 * 2)      // 108544
#define SM_TOT (SM_IX + 64 * 17 * 4)           // 112896 B -> 2 CTAs/SM

#define BBUF(b, a) (SM_BB + ((b) * 2 + (a)) * (128 * BS2 * 2))

__device__ __forceinline__ uint32_t s2u(const void* p) {
    uint32_t a;
    asm("{ .reg .u64 t; cvta.to.shared.u64 t, %1; cvt.u32.u64 %0, t; }"
        : "=r"(a) : "l"(p));
    return a;
}

#define CP16(s, g) \
    asm volatile("cp.async.cg.shared.global [%0], [%1], 16;" :: "r"(s), "l"(g))
#define CP_COMMIT() asm volatile("cp.async.commit_group;" ::: "memory")
#define CP_WAIT1()  asm volatile("cp.async.wait_group 1;" ::: "memory")
#define CP_WAIT0()  asm volatile("cp.async.wait_group 0;" ::: "memory")

#define LDSM4(r, addr) \
    asm volatile("ldmatrix.sync.aligned.m8n8.x4.shared.b16 {%0,%1,%2,%3}, [%4];" \
                 : "=r"((r)[0]), "=r"((r)[1]), "=r"((r)[2]), "=r"((r)[3]) \
                 : "r"(addr))

__device__ __forceinline__ void mma_bf16(float* c, const uint32_t* a,
                                         uint32_t b0, uint32_t b1) {
    asm volatile(
        "mma.sync.aligned.m16n8k16.row.col.f32.bf16.bf16.f32 "
        "{%0,%1,%2,%3}, {%4,%5,%6,%7}, {%8,%9}, {%0,%1,%2,%3};"
        : "+f"(c[0]), "+f"(c[1]), "+f"(c[2]), "+f"(c[3])
        : "r"(a[0]), "r"(a[1]), "r"(a[2]), "r"(a[3]), "r"(b0), "r"(b1));
}

// pack 4 scaled floats into split-bf16 hi/lo and store 8B to each array
__device__ __forceinline__ void put4(__nv_bfloat16* Ah, __nv_bfloat16* Al,
                                     int off, float4 v, float s) {
    float f[4] = {v.x * s, v.y * s, v.z * s, v.w * s};
    uint32_t hp[2], lp[2];
    #pragma unroll
    for (int p = 0; p < 2; p++) {
        __nv_bfloat16 h0 = __float2bfloat16_rn(f[2 * p]);
        __nv_bfloat16 h1 = __float2bfloat16_rn(f[2 * p + 1]);
        float r0 = f[2 * p] - __bfloat162float(h0);
        float r1 = f[2 * p + 1] - __bfloat162float(h1);
        hp[p] = ((uint32_t)__bfloat16_as_ushort(h1) << 16) | __bfloat16_as_ushort(h0);
        lp[p] = ((uint32_t)__bfloat16_as_ushort(__float2bfloat16_rn(r1)) << 16)
              | __bfloat16_as_ushort(__float2bfloat16_rn(r0));
    }
    *(uint2*)&Ah[off] = make_uint2(hp[0], hp[1]);
    *(uint2*)&Al[off] = make_uint2(lp[0], lp[1]);
}

// async-stage one 32-k B chunk (hi+lo) into buffer b
__device__ __forceinline__ void stageB(uint32_t sb, int b, int half, int kc, int tid) {
    const uint32_t dh = sb + BBUF(b, 0);
    const uint32_t dl = sb + BBUF(b, 1);
    #pragma unroll
    for (int r = 0; r < 4; r++) {
        int li = tid + r * 128;          // 0..511
        int row = li >> 2, seg = li & 3;
        size_t gsrc = (size_t)(half * 128 + row) * 256 + kc * 32 + seg * 8;
        uint32_t sa = (uint32_t)(row * (BS2 * 2) + seg * 16);
        CP16(dh + sa, (const char*)&g_Bhi[gsrc]);
        CP16(dl + sa, (const char*)&g_Blo[gsrc]);
    }
}

__global__ void __launch_bounds__(128, 2)
kB_mma(const float* __restrict__ x, const int* __restrict__ nbr,
       const float* __restrict__ bias, float* __restrict__ out, int N)
{
    extern __shared__ char smem[];
    __nv_bfloat16* Ah = (__nv_bfloat16*)(smem + SM_AH);
    __nv_bfloat16* Al = (__nv_bfloat16*)(smem + SM_AL);
    int* sIdx = (int*)(smem + SM_IX);
    const uint32_t sb = s2u(smem);

    const int tid = threadIdx.x;
    const int w = tid >> 5, lane = tid & 31;
    const int nb = blockIdx.x * 64;

    // kick off B chunk 0 immediately (hidden under the whole gather)
    stageB(sb, 0, 0, 0, tid);
    CP_COMMIT();

    // --- neighbor indices ---
    #pragma unroll
    for (int r = 0; r < 8; r++) {
        int li = tid + r * 128;               // 0..1023
        int nl = li >> 4, d = li & 15;
        int src = nb + nl; if (src >= N) src = N - 1;
        sIdx[nl * 17 + d] = nbr[(size_t)src * DDEG + d];
    }
    __syncthreads();

    // --- warp-cooperative gather-mean (fp16 shadow) + self (fp32) ---
    // warp w handles nodes [w*16, w*16+16); all 32 lanes read the SAME row,
    // lane l takes feats [4l, 4l+4): fp16 row = 256B -> 2 lines per LDG.64.
    {
        #pragma unroll 2
        for (int i = 0; i < 16; i++) {
            const int node = w * 16 + i;
            const int* myidx = &sIdx[node * 17];
            int nsrc = nb + node; if (nsrc >= N) nsrc = N - 1;

            float4 a = make_float4(0.f, 0.f, 0.f, 0.f);
            #pragma unroll
            for (int d = 0; d < DDEG; d++) {
                const __half2* p = (const __half2*)(g_xh + (size_t)myidx[d] * FDIM) + lane * 2;
                uint2 u = *(const uint2*)p;
                float2 f01 = __half22float2(*(const __half2*)&u.x);
                float2 f23 = __half22float2(*(const __half2*)&u.y);
                a.x += f01.x; a.y += f01.y; a.z += f23.x; a.w += f23.y;
            }
            float4 sv = *(const float4*)(x + (size_t)nsrc * FDIM + lane * 4);

            put4(Ah, Al, node * AS + 128 + lane * 4, a, 0.0625f);  // nm: k in [128,256)
            put4(Ah, Al, node * AS + lane * 4, sv, 1.0f);          // self: k in [0,128)
        }
    }

    // --- warp tiling: 4 warps = 2(M32) x 2(N64); two 128-wide output halves ---
    const int g = lane >> 2, t = lane & 3;
    const int m0 = (w >> 1) * 32;
    const int n0 = (w & 1) * 64;

    const uint32_t aoff = (uint32_t)(((lane & 15) * AS + ((lane >> 4) << 3)) * 2);
    const uint32_t boff = (uint32_t)((((lane & 7) + ((lane >> 4) << 3)) * BS2
                                      + (((lane >> 3) & 1) << 3)) * 2);

    #pragma unroll
    for (int half = 0; half < 2; half++) {
        float acc[2][8][4];
        #pragma unroll
        for (int mi = 0; mi < 2; mi++)
            #pragma unroll
            for (int j = 0; j < 8; j++)
                #pragma unroll
                for (int c = 0; c < 4; c++) acc[mi][j][c] = 0.f;

        for (int kc = 0; kc < 8; kc++) {
            const int cc = half * 8 + kc;
            if (cc < 15) {
                const int nc = cc + 1;
                stageB(sb, nc & 1, nc >> 3, nc & 7, tid);
                CP_COMMIT();
                CP_WAIT1();              // chunk cc now resident
            } else {
                CP_WAIT0();
            }
            __syncthreads();

            const uint32_t bhB = sb + BBUF(cc & 1, 0);
            const uint32_t blB = sb + BBUF(cc & 1, 1);

            #pragma unroll
            for (int kk = 0; kk < 2; kk++) {
                const int ka = kc * 32 + kk * 16;
                // A fragments
                uint32_t ah[2][4], al[2][4];
                #pragma unroll
                for (int mi = 0; mi < 2; mi++) {
                    uint32_t base = (uint32_t)(((m0 + mi * 16) * AS + ka) * 2) + aoff;
                    LDSM4(ah[mi], sb + SM_AH + base);
                    LDSM4(al[mi], sb + SM_AL + base);
                }
                // B fragments (each x4 covers 2 j's)
                uint32_t bh[8][2], bl[8][2];
                #pragma unroll
                for (int jp = 0; jp < 4; jp++) {
                    uint32_t base = (uint32_t)(((n0 + jp * 16) * BS2 + kk * 16) * 2) + boff;
                    uint32_t tm[4];
                    LDSM4(tm, bhB + base);
                    bh[2 * jp][0] = tm[0]; bh[2 * jp][1] = tm[1];
                    bh[2 * jp + 1][0] = tm[2]; bh[2 * jp + 1][1] = tm[3];
                    LDSM4(tm, blB + base);
                    bl[2 * jp][0] = tm[0]; bl[2 * jp][1] = tm[1];
                    bl[2 * jp + 1][0] = tm[2]; bl[2 * jp + 1][1] = tm[3];
                }
                #pragma unroll
                for (int j = 0; j < 8; j++)
                    #pragma unroll
                    for (int mi = 0; mi < 2; mi++) {
                        mma_bf16(acc[mi][j], ah[mi], bh[j][0], bh[j][1]);  // hi*hi
                        mma_bf16(acc[mi][j], al[mi], bh[j][0], bh[j][1]);  // lo*hi
                        mma_bf16(acc[mi][j], ah[mi], bl[j][0], bl[j][1]);  // hi*lo
                    }
            }
            __syncthreads();
        }

        // --- epilogue for this 128-wide output half (fast ELU) ---
        #pragma unroll
        for (int mi = 0; mi < 2; mi++) {
            int node0 = nb + m0 + mi * 16 + g;
            int node1 = node0 + 8;
            #pragma unroll
            for (int j = 0; j < 8; j++) {
                int o = half * 128 + n0 + j * 8 + 2 * t;
                float2 bv = *(const float2*)&bias[o];
                if (node0 < N) {
                    float t0 = acc[mi][j][0] + bv.x;
                    float t1 = acc[mi][j][1] + bv.y;
                    float2 v;
                    v.x = (t0 > 0.f) ? t0 : (__expf(t0) - 1.0f);
                    v.y = (t1 > 0.f) ? t1 : (__expf(t1) - 1.0f);
                    *(float2*)(out + (size_t)node0 * ODIM + o) = v;
                }
                if (node1 < N) {
                    float t2 = acc[mi][j][2] + bv.x;
                    float t3 = acc[mi][j][3] + bv.y;
                    float2 v;
                    v.x = (t2 > 0.f) ? t2 : (__expf(t2) - 1.0f);
                    v.y = (t3 > 0.f) ? t3 : (__expf(t3) - 1.0f);
                    *(float2*)(out + (size_t)node1 * ODIM + o) = v;
                }
            }
        }
    }
}

// ---------------------------------------------------------------------------
extern "C" void kernel_launch(void* const* d_in, const int* in_sizes, int n_in,
                              void* d_out, int out_size)
{
    const float* x    = (const float*)d_in[0];
    const int*   nbr  = (const int*)  d_in[1];
    const float* R    = (const float*)d_in[2];
    const float* Ws   = (const float*)d_in[3];
    const float* Wn   = (const float*)d_in[4];
    const float* bias = (const float*)d_in[5];
    const int N = in_sizes[0] / FDIM;

    cudaFuncSetAttribute(kB_mma, cudaFuncAttributeMaxDynamicSharedMemorySize, SM_TOT);

    kX<<<592, 256>>>(x, N * FDIM / 2);
    kA<<<dim3(2, 4, 2 * JS), 256>>>(R, Ws, Wn);
    kReduce<<<(2 * FDIM * ODIM) / 256, 256>>>();
    kB_mma<<<(N + 63) / 64, 128, SM_TOT>>>(x, nbr, bias, (float*)d_out, N);
}

// round 8
// speedup vs baseline: 1.2833x; 1.2833x over previous
#include <cuda_runtime.h>
#include <cuda_bf16.h>
#include <math.h>
#include <stdint.h>

// ---------------------------------------------------------------------------
#define FDIM 128
#define DDEG 16
#define KH   2048
#define ODIM 256
#define JS   16
#define JCH  (KH/JS)

// Scratch (device globals; no allocation allowed)
__device__ float g_Mpart[JS][2][FDIM][ODIM];                 // 4 MB partials
__device__ __align__(16) __nv_bfloat16 g_Bhi[ODIM * 256];    // B[o][k] hi
__device__ __align__(16) __nv_bfloat16 g_Blo[ODIM * 256];    // B[o][k] lo

// ---------------------------------------------------------------------------
// Kernel A: partial M[m][f][o] over a 128-wide j chunk (~14us)
// ---------------------------------------------------------------------------
__global__ void __launch_bounds__(256)
kA(const float* __restrict__ R, const float* __restrict__ Ws,
   const float* __restrict__ Wn)
{
    __shared__ float sA[32][68];
    __shared__ float sB[32][68];

    const int ft = blockIdx.x, ot = blockIdx.y, mz = blockIdx.z;
    const int m = mz / JS, jc = mz % JS;
    const float* __restrict__ W = m ? Wn : Ws;
    const int f0 = ft * 64, o0 = ot * 64;
    const int jbase = jc * JCH;
    const int kk = jbase >> 8, hb = jbase & 255;
    const int tid = threadIdx.x, tx = tid & 15, ty = tid >> 4;

    float acc[4][4];
    #pragma unroll
    for (int i = 0; i < 4; i++)
        #pragma unroll
        for (int j = 0; j < 4; j++) acc[i][j] = 0.f;

    for (int jt = 0; jt < JCH; jt += 32) {
        #pragma unroll
        for (int r = 0; r < 2; r++) {
            int li = tid + r * 256;
            int f_l = li >> 3, jj = (li & 7) * 4;
            float4 a4 = *(const float4*)(R + (size_t)kk * (FDIM * 256)
                                           + (size_t)(f0 + f_l) * 256 + hb + jt + jj);
            sA[jj + 0][f_l] = a4.x; sA[jj + 1][f_l] = a4.y;
            sA[jj + 2][f_l] = a4.z; sA[jj + 3][f_l] = a4.w;
        }
        #pragma unroll
        for (int r = 0; r < 2; r++) {
            int li = tid + r * 256;
            int o_l = li >> 3, jj = (li & 7) * 4;
            float4 b4 = *(const float4*)(W + (size_t)(o0 + o_l) * KH + jbase + jt + jj);
            sB[jj + 0][o_l] = b4.x; sB[jj + 1][o_l] = b4.y;
            sB[jj + 2][o_l] = b4.z; sB[jj + 3][o_l] = b4.w;
        }
        __syncthreads();
        #pragma unroll
        for (int jj = 0; jj < 32; jj++) {
            float4 a4 = *(const float4*)&sA[jj][ty * 4];
            float4 b4 = *(const float4*)&sB[jj][tx * 4];
            float a[4] = {a4.x, a4.y, a4.z, a4.w};
            float b[4] = {b4.x, b4.y, b4.z, b4.w};
            #pragma unroll
            for (int i = 0; i < 4; i++)
                #pragma unroll
                for (int j = 0; j < 4; j++) acc[i][j] += a[i] * b[j];
        }
        __syncthreads();
    }
    float* outp = &g_Mpart[jc][m][0][0];
    #pragma unroll
    for (int i = 0; i < 4; i++) {
        float4 v = make_float4(acc[i][0], acc[i][1], acc[i][2], acc[i][3]);
        *(float4*)(outp + (size_t)(f0 + ty * 4 + i) * ODIM + o0 + tx * 4) = v;
    }
}

// Reduce partials, split to bf16 hi/lo, transpose to B[o][k], k = m*128+f.
__global__ void __launch_bounds__(256)
kReduce()
{
    int i = blockIdx.x * 256 + threadIdx.x;  // [m][f][o]
    const float* p = (const float*)g_Mpart;
    float s = 0.f;
    #pragma unroll
    for (int q = 0; q < JS; q++) s += p[(size_t)q * 2 * FDIM * ODIM + i];
    int m = i >> 15, f = (i >> 8) & 127, o = i & 255;
    int k = m * 128 + f;
    __nv_bfloat16 h = __float2bfloat16_rn(s);
    float r = s - __bfloat162float(h);
    g_Bhi[o * 256 + k] = h;
    g_Blo[o * 256 + k] = __float2bfloat16_rn(r);
}

// ---------------------------------------------------------------------------
// kB_mma: 64 nodes/CTA, 256 threads (8 warps), 2 CTAs/SM -> 16 warps/SM.
//   Gather: warp-cooperative fp32 (4 lines/LDG), 8 nodes/warp.
//   B:      cp.async double-buffered 32-k chunks.
//   GEMM:   8 warps = 2(M32) x 4(N32); ldmatrix + 3-pass split-bf16 HMMA.
// ---------------------------------------------------------------------------
#define AS 264   // A smem row stride (bf16): conflict-free LDSM
#define BS2 40   // B chunk smem row stride (bf16): conflict-free LDSM

#define SM_AH 0
#define SM_AL (SM_AH + 64 * AS * 2)            // 33792
#define SM_BB (SM_AL + 64 * AS * 2)            // 67584: 4 x (128*BS2*2 = 10240)
#define SM_IX (SM_BB + 4 * 128 * BS2 * 2)      // 108544
#define SM_TOT (SM_IX + 64 * 17 * 4)           // 112896 B -> 2 CTAs/SM

#define BBUF(b, a) (SM_BB + ((b) * 2 + (a)) * (128 * BS2 * 2))

__device__ __forceinline__ uint32_t s2u(const void* p) {
    uint32_t a;
    asm("{ .reg .u64 t; cvta.to.shared.u64 t, %1; cvt.u32.u64 %0, t; }"
        : "=r"(a) : "l"(p));
    return a;
}

#define CP16(s, g) \
    asm volatile("cp.async.cg.shared.global [%0], [%1], 16;" :: "r"(s), "l"(g))
#define CP_COMMIT() asm volatile("cp.async.commit_group;" ::: "memory")
#define CP_WAIT1()  asm volatile("cp.async.wait_group 1;" ::: "memory")
#define CP_WAIT0()  asm volatile("cp.async.wait_group 0;" ::: "memory")

#define LDSM4(r, addr) \
    asm volatile("ldmatrix.sync.aligned.m8n8.x4.shared.b16 {%0,%1,%2,%3}, [%4];" \
                 : "=r"((r)[0]), "=r"((r)[1]), "=r"((r)[2]), "=r"((r)[3]) \
                 : "r"(addr))

__device__ __forceinline__ void mma_bf16(float* c, const uint32_t* a,
                                         uint32_t b0, uint32_t b1) {
    asm volatile(
        "mma.sync.aligned.m16n8k16.row.col.f32.bf16.bf16.f32 "
        "{%0,%1,%2,%3}, {%4,%5,%6,%7}, {%8,%9}, {%0,%1,%2,%3};"
        : "+f"(c[0]), "+f"(c[1]), "+f"(c[2]), "+f"(c[3])
        : "r"(a[0]), "r"(a[1]), "r"(a[2]), "r"(a[3]), "r"(b0), "r"(b1));
}

// pack 4 scaled floats into split-bf16 hi/lo and store 8B to each array
__device__ __forceinline__ void put4(__nv_bfloat16* Ah, __nv_bfloat16* Al,
                                     int off, float4 v, float s) {
    float f[4] = {v.x * s, v.y * s, v.z * s, v.w * s};
    uint32_t hp[2], lp[2];
    #pragma unroll
    for (int p = 0; p < 2; p++) {
        __nv_bfloat16 h0 = __float2bfloat16_rn(f[2 * p]);
        __nv_bfloat16 h1 = __float2bfloat16_rn(f[2 * p + 1]);
        float r0 = f[2 * p] - __bfloat162float(h0);
        float r1 = f[2 * p + 1] - __bfloat162float(h1);
        hp[p] = ((uint32_t)__bfloat16_as_ushort(h1) << 16) | __bfloat16_as_ushort(h0);
        lp[p] = ((uint32_t)__bfloat16_as_ushort(__float2bfloat16_rn(r1)) << 16)
              | __bfloat16_as_ushort(__float2bfloat16_rn(r0));
    }
    *(uint2*)&Ah[off] = make_uint2(hp[0], hp[1]);
    *(uint2*)&Al[off] = make_uint2(lp[0], lp[1]);
}

// async-stage one 32-k B chunk (hi+lo) into buffer b (256 threads)
__device__ __forceinline__ void stageB(uint32_t sb, int b, int half, int kc, int tid) {
    const uint32_t dh = sb + BBUF(b, 0);
    const uint32_t dl = sb + BBUF(b, 1);
    #pragma unroll
    for (int r = 0; r < 2; r++) {
        int li = tid + r * 256;          // 0..511
        int row = li >> 2, seg = li & 3;
        size_t gsrc = (size_t)(half * 128 + row) * 256 + kc * 32 + seg * 8;
        uint32_t sa = (uint32_t)(row * (BS2 * 2) + seg * 16);
        CP16(dh + sa, (const char*)&g_Bhi[gsrc]);
        CP16(dl + sa, (const char*)&g_Blo[gsrc]);
    }
}

__global__ void __launch_bounds__(256, 2)
kB_mma(const float* __restrict__ x, const int* __restrict__ nbr,
       const float* __restrict__ bias, float* __restrict__ out, int N)
{
    extern __shared__ char smem[];
    __nv_bfloat16* Ah = (__nv_bfloat16*)(smem + SM_AH);
    __nv_bfloat16* Al = (__nv_bfloat16*)(smem + SM_AL);
    int* sIdx = (int*)(smem + SM_IX);
    const uint32_t sb = s2u(smem);

    const int tid = threadIdx.x;
    const int w = tid >> 5, lane = tid & 31;
    const int nb = blockIdx.x * 64;

    // kick off B chunk 0 immediately (hidden under the whole gather)
    stageB(sb, 0, 0, 0, tid);
    CP_COMMIT();

    // --- neighbor indices ---
    #pragma unroll
    for (int r = 0; r < 4; r++) {
        int li = tid + r * 256;               // 0..1023
        int nl = li >> 4, d = li & 15;
        int src = nb + nl; if (src >= N) src = N - 1;
        sIdx[nl * 17 + d] = nbr[(size_t)src * DDEG + d];
    }
    __syncthreads();

    // --- warp-cooperative gather-mean + self -> split-bf16 A ---
    // warp w handles nodes [w*8, w*8+8); all 32 lanes read the SAME row,
    // lane l takes feats [4l, 4l+4) -> each LDG.128 touches only 4 lines.
    {
        #pragma unroll 2
        for (int i = 0; i < 8; i++) {
            const int node = w * 8 + i;
            const int* myidx = &sIdx[node * 17];
            int nsrc = nb + node; if (nsrc >= N) nsrc = N - 1;

            float4 a = make_float4(0.f, 0.f, 0.f, 0.f);
            #pragma unroll
            for (int d = 0; d < DDEG; d++) {
                float4 v = *(const float4*)(x + (size_t)myidx[d] * FDIM + lane * 4);
                a.x += v.x; a.y += v.y; a.z += v.z; a.w += v.w;
            }
            float4 sv = *(const float4*)(x + (size_t)nsrc * FDIM + lane * 4);

            put4(Ah, Al, node * AS + 128 + lane * 4, a, 0.0625f);  // nm: k in [128,256)
            put4(Ah, Al, node * AS + lane * 4, sv, 1.0f);          // self: k in [0,128)
        }
    }

    // --- warp tiling: 8 warps = 2(M32) x 4(N32); two 128-wide output halves ---
    const int g = lane >> 2, t = lane & 3;
    const int m0 = (w >> 2) * 32;
    const int n0 = (w & 3) * 32;

    const uint32_t aoff = (uint32_t)(((lane & 15) * AS + ((lane >> 4) << 3)) * 2);
    const uint32_t boff = (uint32_t)((((lane & 7) + ((lane >> 4) << 3)) * BS2
                                      + (((lane >> 3) & 1) << 3)) * 2);

    #pragma unroll
    for (int half = 0; half < 2; half++) {
        float acc[2][4][4];
        #pragma unroll
        for (int mi = 0; mi < 2; mi++)
            #pragma unroll
            for (int j = 0; j < 4; j++)
                #pragma unroll
                for (int c = 0; c < 4; c++) acc[mi][j][c] = 0.f;

        for (int kc = 0; kc < 8; kc++) {
            const int cc = half * 8 + kc;
            if (cc < 15) {
                const int nc = cc + 1;
                stageB(sb, nc & 1, nc >> 3, nc & 7, tid);
                CP_COMMIT();
                CP_WAIT1();              // chunk cc now resident
            } else {
                CP_WAIT0();
            }
            __syncthreads();

            const uint32_t bhB = sb + BBUF(cc & 1, 0);
            const uint32_t blB = sb + BBUF(cc & 1, 1);

            #pragma unroll
            for (int kk = 0; kk < 2; kk++) {
                const int ka = kc * 32 + kk * 16;
                // A fragments
                uint32_t ah[2][4], al[2][4];
                #pragma unroll
                for (int mi = 0; mi < 2; mi++) {
                    uint32_t base = (uint32_t)(((m0 + mi * 16) * AS + ka) * 2) + aoff;
                    LDSM4(ah[mi], sb + SM_AH + base);
                    LDSM4(al[mi], sb + SM_AL + base);
                }
                // B fragments (each x4 covers 2 j's)
                uint32_t bh[4][2], bl[4][2];
                #pragma unroll
                for (int jp = 0; jp < 2; jp++) {
                    uint32_t base = (uint32_t)(((n0 + jp * 16) * BS2 + kk * 16) * 2) + boff;
                    uint32_t tm[4];
                    LDSM4(tm, bhB + base);
                    bh[2 * jp][0] = tm[0]; bh[2 * jp][1] = tm[1];
                    bh[2 * jp + 1][0] = tm[2]; bh[2 * jp + 1][1] = tm[3];
                    LDSM4(tm, blB + base);
                    bl[2 * jp][0] = tm[0]; bl[2 * jp][1] = tm[1];
                    bl[2 * jp + 1][0] = tm[2]; bl[2 * jp + 1][1] = tm[3];
                }
                #pragma unroll
                for (int j = 0; j < 4; j++)
                    #pragma unroll
                    for (int mi = 0; mi < 2; mi++) {
                        mma_bf16(acc[mi][j], ah[mi], bh[j][0], bh[j][1]);  // hi*hi
                        mma_bf16(acc[mi][j], al[mi], bh[j][0], bh[j][1]);  // lo*hi
                        mma_bf16(acc[mi][j], ah[mi], bl[j][0], bl[j][1]);  // hi*lo
                    }
            }
            __syncthreads();
        }

        // --- epilogue for this 128-wide output half (fast ELU) ---
        #pragma unroll
        for (int mi = 0; mi < 2; mi++) {
            int node0 = nb + m0 + mi * 16 + g;
            int node1 = node0 + 8;
            #pragma unroll
            for (int j = 0; j < 4; j++) {
                int o = half * 128 + n0 + j * 8 + 2 * t;
                float2 bv = *(const float2*)&bias[o];
                if (node0 < N) {
                    float t0 = acc[mi][j][0] + bv.x;
                    float t1 = acc[mi][j][1] + bv.y;
                    float2 v;
                    v.x = (t0 > 0.f) ? t0 : (__expf(t0) - 1.0f);
                    v.y = (t1 > 0.f) ? t1 : (__expf(t1) - 1.0f);
                    *(float2*)(out + (size_t)node0 * ODIM + o) = v;
                }
                if (node1 < N) {
                    float t2 = acc[mi][j][2] + bv.x;
                    float t3 = acc[mi][j][3] + bv.y;
                    float2 v;
                    v.x = (t2 > 0.f) ? t2 : (__expf(t2) - 1.0f);
                    v.y = (t3 > 0.f) ? t3 : (__expf(t3) - 1.0f);
                    *(float2*)(out + (size_t)node1 * ODIM + o) = v;
                }
            }
        }
    }
}

// ---------------------------------------------------------------------------
extern "C" void kernel_launch(void* const* d_in, const int* in_sizes, int n_in,
                              void* d_out, int out_size)
{
    const float* x    = (const float*)d_in[0];
    const int*   nbr  = (const int*)  d_in[1];
    const float* R    = (const float*)d_in[2];
    const float* Ws   = (const float*)d_in[3];
    const float* Wn   = (const float*)d_in[4];
    const float* bias = (const float*)d_in[5];
    const int N = in_sizes[0] / FDIM;

    cudaFuncSetAttribute(kB_mma, cudaFuncAttributeMaxDynamicSharedMemorySize, SM_TOT);

    kA<<<dim3(2, 4, 2 * JS), 256>>>(R, Ws, Wn);
    kReduce<<<(2 * FDIM * ODIM) / 256, 256>>>();
    kB_mma<<<(N + 63) / 64, 256, SM_TOT>>>(x, nbr, bias, (float*)d_out, N);
}

// round 9
// speedup vs baseline: 1.3102x; 1.0210x over previous
#include <cuda_runtime.h>
#include <cuda_bf16.h>
#include <math.h>
#include <stdint.h>

// ---------------------------------------------------------------------------
#define FDIM 128
#define DDEG 16
#define KH   2048
#define ODIM 256
#define JS   16
#define JCH  (KH/JS)

// Scratch (device globals; no allocation allowed)
__device__ float g_Mpart[JS][2][FDIM][ODIM];                 // 4 MB partials
__device__ __align__(16) __nv_bfloat16 g_Bhi[ODIM * 256];    // B[o][k] hi
__device__ __align__(16) __nv_bfloat16 g_Blo[ODIM * 256];    // B[o][k] lo

// ---------------------------------------------------------------------------
// Kernel A: partial M[m][f][o] over a 128-wide j chunk (~14us)
// ---------------------------------------------------------------------------
__global__ void __launch_bounds__(256)
kA(const float* __restrict__ R, const float* __restrict__ Ws,
   const float* __restrict__ Wn)
{
    __shared__ float sA[32][68];
    __shared__ float sB[32][68];

    const int ft = blockIdx.x, ot = blockIdx.y, mz = blockIdx.z;
    const int m = mz / JS, jc = mz % JS;
    const float* __restrict__ W = m ? Wn : Ws;
    const int f0 = ft * 64, o0 = ot * 64;
    const int jbase = jc * JCH;
    const int kk = jbase >> 8, hb = jbase & 255;
    const int tid = threadIdx.x, tx = tid & 15, ty = tid >> 4;

    float acc[4][4];
    #pragma unroll
    for (int i = 0; i < 4; i++)
        #pragma unroll
        for (int j = 0; j < 4; j++) acc[i][j] = 0.f;

    for (int jt = 0; jt < JCH; jt += 32) {
        #pragma unroll
        for (int r = 0; r < 2; r++) {
            int li = tid + r * 256;
            int f_l = li >> 3, jj = (li & 7) * 4;
            float4 a4 = *(const float4*)(R + (size_t)kk * (FDIM * 256)
                                           + (size_t)(f0 + f_l) * 256 + hb + jt + jj);
            sA[jj + 0][f_l] = a4.x; sA[jj + 1][f_l] = a4.y;
            sA[jj + 2][f_l] = a4.z; sA[jj + 3][f_l] = a4.w;
        }
        #pragma unroll
        for (int r = 0; r < 2; r++) {
            int li = tid + r * 256;
            int o_l = li >> 3, jj = (li & 7) * 4;
            float4 b4 = *(const float4*)(W + (size_t)(o0 + o_l) * KH + jbase + jt + jj);
            sB[jj + 0][o_l] = b4.x; sB[jj + 1][o_l] = b4.y;
            sB[jj + 2][o_l] = b4.z; sB[jj + 3][o_l] = b4.w;
        }
        __syncthreads();
        #pragma unroll
        for (int jj = 0; jj < 32; jj++) {
            float4 a4 = *(const float4*)&sA[jj][ty * 4];
            float4 b4 = *(const float4*)&sB[jj][tx * 4];
            float a[4] = {a4.x, a4.y, a4.z, a4.w};
            float b[4] = {b4.x, b4.y, b4.z, b4.w};
            #pragma unroll
            for (int i = 0; i < 4; i++)
                #pragma unroll
                for (int j = 0; j < 4; j++) acc[i][j] += a[i] * b[j];
        }
        __syncthreads();
    }
    float* outp = &g_Mpart[jc][m][0][0];
    #pragma unroll
    for (int i = 0; i < 4; i++) {
        float4 v = make_float4(acc[i][0], acc[i][1], acc[i][2], acc[i][3]);
        *(float4*)(outp + (size_t)(f0 + ty * 4 + i) * ODIM + o0 + tx * 4) = v;
    }
}

// Reduce partials, split to bf16 hi/lo, transpose to B[o][k], k = m*128+f.
__global__ void __launch_bounds__(256)
kReduce()
{
    int i = blockIdx.x * 256 + threadIdx.x;  // [m][f][o]
    const float* p = (const float*)g_Mpart;
    float s = 0.f;
    #pragma unroll
    for (int q = 0; q < JS; q++) s += p[(size_t)q * 2 * FDIM * ODIM + i];
    int m = i >> 15, f = (i >> 8) & 127, o = i & 255;
    int k = m * 128 + f;
    __nv_bfloat16 h = __float2bfloat16_rn(s);
    float r = s - __bfloat162float(h);
    g_Bhi[o * 256 + k] = h;
    g_Blo[o * 256 + k] = __float2bfloat16_rn(r);
}

// ---------------------------------------------------------------------------
// kB_mma: persistent warp-specialized pipeline. 512 threads, 1 CTA/SM.
//   warps 0-7  (consumers): ldmatrix + 3-pass split-bf16 HMMA + epilogue.
//   warps 8-15 (producers): warp-cooperative gather into double-buffered A.
//   Handshake: named barriers FULL/EMPTY per A buffer.
// ---------------------------------------------------------------------------
#define AS 264   // A smem row stride (bf16): conflict-free LDSM
#define BS2 40   // B chunk smem row stride (bf16): conflict-free LDSM

#define A_BUF_SZ (64 * AS * 2 * 2)             // Ah+Al per buffer = 67584
#define SM_BB    (2 * A_BUF_SZ)                // 135168: 4 x 10240
#define SM_IX    (SM_BB + 4 * 128 * BS2 * 2)   // 176128: 2 x 4352
#define SM_TOT   (SM_IX + 2 * 64 * 17 * 4)     // 184832 B -> 1 CTA/SM

#define BBUF(b, a) (SM_BB + ((b) * 2 + (a)) * (128 * BS2 * 2))

// named barrier ids
#define BAR_FULL0  1
#define BAR_EMPTY0 3
#define BAR_PROD   5
#define BAR_CONS   6

#define BARSYNC(id, cnt) \
    asm volatile("bar.sync %0, %1;" :: "r"(id), "r"(cnt) : "memory")
#define BARARRIVE(id, cnt) \
    asm volatile("bar.arrive %0, %1;" :: "r"(id), "r"(cnt) : "memory")

__device__ __forceinline__ uint32_t s2u(const void* p) {
    uint32_t a;
    asm("{ .reg .u64 t; cvta.to.shared.u64 t, %1; cvt.u32.u64 %0, t; }"
        : "=r"(a) : "l"(p));
    return a;
}

#define CP16(s, g) \
    asm volatile("cp.async.cg.shared.global [%0], [%1], 16;" :: "r"(s), "l"(g))
#define CP_COMMIT() asm volatile("cp.async.commit_group;" ::: "memory")
#define CP_WAIT1()  asm volatile("cp.async.wait_group 1;" ::: "memory")
#define CP_WAIT0()  asm volatile("cp.async.wait_group 0;" ::: "memory")

#define LDSM4(r, addr) \
    asm volatile("ldmatrix.sync.aligned.m8n8.x4.shared.b16 {%0,%1,%2,%3}, [%4];" \
                 : "=r"((r)[0]), "=r"((r)[1]), "=r"((r)[2]), "=r"((r)[3]) \
                 : "r"(addr))

__device__ __forceinline__ void mma_bf16(float* c, const uint32_t* a,
                                         uint32_t b0, uint32_t b1) {
    asm volatile(
        "mma.sync.aligned.m16n8k16.row.col.f32.bf16.bf16.f32 "
        "{%0,%1,%2,%3}, {%4,%5,%6,%7}, {%8,%9}, {%0,%1,%2,%3};"
        : "+f"(c[0]), "+f"(c[1]), "+f"(c[2]), "+f"(c[3])
        : "r"(a[0]), "r"(a[1]), "r"(a[2]), "r"(a[3]), "r"(b0), "r"(b1));
}

// pack 4 scaled floats into split-bf16 hi/lo and store 8B to each array
__device__ __forceinline__ void put4(__nv_bfloat16* Ah, __nv_bfloat16* Al,
                                     int off, float4 v, float s) {
    float f[4] = {v.x * s, v.y * s, v.z * s, v.w * s};
    uint32_t hp[2], lp[2];
    #pragma unroll
    for (int p = 0; p < 2; p++) {
        __nv_bfloat16 h0 = __float2bfloat16_rn(f[2 * p]);
        __nv_bfloat16 h1 = __float2bfloat16_rn(f[2 * p + 1]);
        float r0 = f[2 * p] - __bfloat162float(h0);
        float r1 = f[2 * p + 1] - __bfloat162float(h1);
        hp[p] = ((uint32_t)__bfloat16_as_ushort(h1) << 16) | __bfloat16_as_ushort(h0);
        lp[p] = ((uint32_t)__bfloat16_as_ushort(__float2bfloat16_rn(r1)) << 16)
              | __bfloat16_as_ushort(__float2bfloat16_rn(r0));
    }
    *(uint2*)&Ah[off] = make_uint2(hp[0], hp[1]);
    *(uint2*)&Al[off] = make_uint2(lp[0], lp[1]);
}

// async-stage one 32-k B chunk (hi+lo) into buffer b (256 consumer threads)
__device__ __forceinline__ void stageB(uint32_t sb, int b, int half, int kc, int ctid) {
    const uint32_t dh = sb + BBUF(b, 0);
    const uint32_t dl = sb + BBUF(b, 1);
    #pragma unroll
    for (int r = 0; r < 2; r++) {
        int li = ctid + r * 256;         // 0..511
        int row = li >> 2, seg = li & 3;
        size_t gsrc = (size_t)(half * 128 + row) * 256 + kc * 32 + seg * 8;
        uint32_t sa = (uint32_t)(row * (BS2 * 2) + seg * 16);
        CP16(dh + sa, (const char*)&g_Bhi[gsrc]);
        CP16(dl + sa, (const char*)&g_Blo[gsrc]);
    }
}

__global__ void __launch_bounds__(512, 1)
kB_mma(const float* __restrict__ x, const int* __restrict__ nbr,
       const float* __restrict__ bias, float* __restrict__ out, int N)
{
    extern __shared__ char smem[];
    const uint32_t sb = s2u(smem);
    const int tid = threadIdx.x;
    const int lane = tid & 31;
    const int NT = (N + 63) >> 6;
    const int G = gridDim.x;

    if (tid >= 256) {
        // ===================== PRODUCER (warps 8..15) =====================
        const int pw = (tid >> 5) - 8;       // 0..7
        const int ptid = tid - 256;          // 0..255
        int i = 0;
        for (int tile = blockIdx.x; tile < NT; tile += G, i++) {
            const int p = i & 1;
            const int nb = tile * 64;
            __nv_bfloat16* Ah = (__nv_bfloat16*)(smem + p * A_BUF_SZ);
            __nv_bfloat16* Al = (__nv_bfloat16*)(smem + p * A_BUF_SZ + 64 * AS * 2);
            int* sIdx = (int*)(smem + SM_IX + p * 4352);

            // stage neighbor indices for this tile (256 producer threads)
            #pragma unroll
            for (int r = 0; r < 4; r++) {
                int li = ptid + r * 256;     // 0..1023
                int nl = li >> 4, d = li & 15;
                int src = nb + nl; if (src >= N) src = N - 1;
                sIdx[nl * 17 + d] = nbr[(size_t)src * DDEG + d];
            }
            BARSYNC(BAR_PROD, 256);          // idx visible to all producers
            if (i >= 2) BARSYNC(BAR_EMPTY0 + p, 512);  // buffer free?

            // warp-cooperative gather-mean + self -> split-bf16 A[p]
            #pragma unroll 2
            for (int q = 0; q < 8; q++) {
                const int node = pw * 8 + q;
                const int* myidx = &sIdx[node * 17];
                int nsrc = nb + node; if (nsrc >= N) nsrc = N - 1;

                float4 a = make_float4(0.f, 0.f, 0.f, 0.f);
                #pragma unroll
                for (int d = 0; d < DDEG; d++) {
                    float4 v = *(const float4*)(x + (size_t)myidx[d] * FDIM + lane * 4);
                    a.x += v.x; a.y += v.y; a.z += v.z; a.w += v.w;
                }
                float4 sv = *(const float4*)(x + (size_t)nsrc * FDIM + lane * 4);

                put4(Ah, Al, node * AS + 128 + lane * 4, a, 0.0625f); // nm
                put4(Ah, Al, node * AS + lane * 4, sv, 1.0f);         // self
            }
            BARARRIVE(BAR_FULL0 + p, 512);   // A[p] full
        }
    } else {
        // ===================== CONSUMER (warps 0..7) ======================
        const int w = tid >> 5;              // 0..7
        const int ctid = tid;                // 0..255
        const int g = lane >> 2, t = lane & 3;
        const int m0 = (w >> 2) * 32;
        const int n0 = (w & 3) * 32;

        const uint32_t aoff = (uint32_t)(((lane & 15) * AS + ((lane >> 4) << 3)) * 2);
        const uint32_t boff = (uint32_t)((((lane & 7) + ((lane >> 4) << 3)) * BS2
                                          + (((lane >> 3) & 1) << 3)) * 2);

        // prefetch B chunk 0 of first tile
        if (blockIdx.x < NT) { stageB(sb, 0, 0, 0, ctid); CP_COMMIT(); }

        int i = 0;
        for (int tile = blockIdx.x; tile < NT; tile += G, i++) {
            const int p = i & 1;
            const int nb = tile * 64;
            const uint32_t aBase = sb + (uint32_t)(p * A_BUF_SZ);
            const bool moreTiles = (tile + G) < NT;

            BARSYNC(BAR_FULL0 + p, 512);     // wait A[p]

            #pragma unroll
            for (int half = 0; half < 2; half++) {
                float acc[2][4][4];
                #pragma unroll
                for (int mi = 0; mi < 2; mi++)
                    #pragma unroll
                    for (int j = 0; j < 4; j++)
                        #pragma unroll
                        for (int c = 0; c < 4; c++) acc[mi][j][c] = 0.f;

                for (int kc = 0; kc < 8; kc++) {
                    const int cc = half * 8 + kc;
                    if (cc < 15) {
                        const int nc = cc + 1;
                        stageB(sb, nc & 1, nc >> 3, nc & 7, ctid);
                        CP_COMMIT();
                        CP_WAIT1();          // chunk cc resident
                    } else if (moreTiles) {
                        stageB(sb, 0, 0, 0, ctid);   // chunk0 of next tile
                        CP_COMMIT();
                        CP_WAIT1();
                    } else {
                        CP_WAIT0();
                    }
                    BARSYNC(BAR_CONS, 256);

                    const uint32_t bhB = sb + BBUF(cc & 1, 0);
                    const uint32_t blB = sb + BBUF(cc & 1, 1);

                    #pragma unroll
                    for (int kk = 0; kk < 2; kk++) {
                        const int ka = kc * 32 + kk * 16;
                        uint32_t ah[2][4], al[2][4];
                        #pragma unroll
                        for (int mi = 0; mi < 2; mi++) {
                            uint32_t base = (uint32_t)(((m0 + mi * 16) * AS + ka) * 2) + aoff;
                            LDSM4(ah[mi], aBase + base);
                            LDSM4(al[mi], aBase + (uint32_t)(64 * AS * 2) + base);
                        }
                        uint32_t bh[4][2], bl[4][2];
                        #pragma unroll
                        for (int jp = 0; jp < 2; jp++) {
                            uint32_t base = (uint32_t)(((n0 + jp * 16) * BS2 + kk * 16) * 2) + boff;
                            uint32_t tm[4];
                            LDSM4(tm, bhB + base);
                            bh[2 * jp][0] = tm[0]; bh[2 * jp][1] = tm[1];
                            bh[2 * jp + 1][0] = tm[2]; bh[2 * jp + 1][1] = tm[3];
                            LDSM4(tm, blB + base);
                            bl[2 * jp][0] = tm[0]; bl[2 * jp][1] = tm[1];
                            bl[2 * jp + 1][0] = tm[2]; bl[2 * jp + 1][1] = tm[3];
                        }
                        #pragma unroll
                        for (int j = 0; j < 4; j++)
                            #pragma unroll
                            for (int mi = 0; mi < 2; mi++) {
                                mma_bf16(acc[mi][j], ah[mi], bh[j][0], bh[j][1]);
                                mma_bf16(acc[mi][j], al[mi], bh[j][0], bh[j][1]);
                                mma_bf16(acc[mi][j], ah[mi], bl[j][0], bl[j][1]);
                            }
                    }
                    BARSYNC(BAR_CONS, 256);
                }

                if (half == 1) BARARRIVE(BAR_EMPTY0 + p, 512);  // A[p] free

                // epilogue for this 128-wide output half (fast ELU)
                #pragma unroll
                for (int mi = 0; mi < 2; mi++) {
                    int node0 = nb + m0 + mi * 16 + g;
                    int node1 = node0 + 8;
                    #pragma unroll
                    for (int j = 0; j < 4; j++) {
                        int o = half * 128 + n0 + j * 8 + 2 * t;
                        float2 bv = *(const float2*)&bias[o];
                        if (node0 < N) {
                            float t0 = acc[mi][j][0] + bv.x;
                            float t1 = acc[mi][j][1] + bv.y;
                            float2 v;
                            v.x = (t0 > 0.f) ? t0 : (__expf(t0) - 1.0f);
                            v.y = (t1 > 0.f) ? t1 : (__expf(t1) - 1.0f);
                            *(float2*)(out + (size_t)node0 * ODIM + o) = v;
                        }
                        if (node1 < N) {
                            float t2 = acc[mi][j][2] + bv.x;
                            float t3 = acc[mi][j][3] + bv.y;
                            float2 v;
                            v.x = (t2 > 0.f) ? t2 : (__expf(t2) - 1.0f);
                            v.y = (t3 > 0.f) ? t3 : (__expf(t3) - 1.0f);
                            *(float2*)(out + (size_t)node1 * ODIM + o) = v;
                        }
                    }
                }
            }
        }
    }
}

// ---------------------------------------------------------------------------
extern "C" void kernel_launch(void* const* d_in, const int* in_sizes, int n_in,
                              void* d_out, int out_size)
{
    const float* x    = (const float*)d_in[0];
    const int*   nbr  = (const int*)  d_in[1];
    const float* R    = (const float*)d_in[2];
    const float* Ws   = (const float*)d_in[3];
    const float* Wn   = (const float*)d_in[4];
    const float* bias = (const float*)d_in[5];
    const int N = in_sizes[0] / FDIM;

    static int nsm = 0;
    if (nsm == 0) {
        cudaDeviceGetAttribute(&nsm, cudaDevAttrMultiProcessorCount, 0);
        if (nsm <= 0) nsm = 148;
        cudaFuncSetAttribute(kB_mma, cudaFuncAttributeMaxDynamicSharedMemorySize, SM_TOT);
    }

    kA<<<dim3(2, 4, 2 * JS), 256>>>(R, Ws, Wn);
    kReduce<<<(2 * FDIM * ODIM) / 256, 256>>>();
    kB_mma<<<nsm, 512, SM_TOT>>>(x, nbr, bias, (float*)d_out, N);
}